// round 16
// baseline (speedup 1.0000x reference)
#include <cuda_runtime.h>

#define EPSF 1e-6f
#define S 32
#define C 3
#define TILE (S * S)   // 1024
#define PAD 33

// Tridiagonal tables (7): 0 = X @ t=0.0, 1 = X @ t=0.5, 2+k = Y @ t=0.05+0.1k
//   g_tri[(tab*C+c)*TILE + i*S + r] = (invd, w);  bwd: x_i = d_i + w_i x_{i+1}
// Pentadiagonal tables (4): k = 0..3 for the doubled X solve @ t=0.1*(k+1)
//   g_p4[(k*C+c)*TILE + i*S + r] = (inv0, nl1, nl2, nw1)
//   g_p1[(k*C+c)*TILE + i*S + r] = nw2
// fwd: e_i = u_i*inv0 + nl1*e_{i-1} + nl2*e_{i-2}
// bwd: x_i = e_i + nw1*x_{i+1} + nw2*x_{i+2}
__device__ __align__(128) float2 g_tri[7 * C * TILE];
__device__ __align__(128) float4 g_p4 [4 * C * TILE];
__device__ __align__(128) float  g_p1 [4 * C * TILE];

// ---------------------------------------------------------------------------
// packed f32x2 helpers (PTX-only; ptxas never auto-fuses)
// ---------------------------------------------------------------------------
__device__ __forceinline__ float2 fma2(float2 a, float2 b, float2 c) {
    unsigned long long au = *reinterpret_cast<unsigned long long*>(&a);
    unsigned long long bu = *reinterpret_cast<unsigned long long*>(&b);
    unsigned long long cu = *reinterpret_cast<unsigned long long*>(&c);
    unsigned long long du;
    asm("fma.rn.f32x2 %0, %1, %2, %3;" : "=l"(du) : "l"(au), "l"(bu), "l"(cu));
    return *reinterpret_cast<float2*>(&du);
}
__device__ __forceinline__ float2 mul2(float2 a, float2 b) {
    unsigned long long au = *reinterpret_cast<unsigned long long*>(&a);
    unsigned long long bu = *reinterpret_cast<unsigned long long*>(&b);
    unsigned long long du;
    asm("mul.rn.f32x2 %0, %1, %2;" : "=l"(du) : "l"(au), "l"(bu));
    return *reinterpret_cast<float2*>(&du);
}

// ---------------------------------------------------------------------------
// Precompute: one thread per (table, c, row). 11*3*32 = 1056 threads.
// Tables 0..6 tridiagonal; 7..10 pentadiagonal (squared X operator).
// ---------------------------------------------------------------------------
__global__ void precompute_kernel(const float* __restrict__ ab,
                                  const float* __restrict__ bb,
                                  const float* __restrict__ atc,
                                  const float* __restrict__ btc) {
    int tid = blockIdx.x * blockDim.x + threadIdx.x;
    if (tid >= 11 * C * S) return;
    int tab = tid / (C * S);
    int rem = tid % (C * S);
    int c   = rem / S;
    int r   = rem % S;

    // direction / time / coefficient source
    bool isx;
    float t, fac;
    if (tab < 7) {
        isx = (tab < 2);
        t   = isx ? (tab == 0 ? 0.0f : 0.5f) : (0.05f + 0.1f * (tab - 2));
    } else {
        isx = true;
        t   = 0.1f * (tab - 6);      // k=tab-7 -> t=0.1*(k+1)
    }
    fac = isx ? 0.05f : 0.1f;
    const float* bp = isx ? (ab  + (c * S + r) * S) : (bb  + c * TILE + r);
    const float* tp = isx ? (atc + (c * S + r) * S) : (btc + c * TILE + r);
    const int stride = isx ? 1 : S;

    float coef[S];
#pragma unroll
    for (int i = 0; i < S; ++i)
        coef[i] = fmaxf(bp[i * stride] + t * tp[i * stride], EPSF);

    float cs[S];
    cs[0] = (coef[0] + coef[0] + coef[1]) / 3.0f * fac;
#pragma unroll
    for (int i = 1; i < S - 1; ++i)
        cs[i] = (coef[i - 1] + coef[i] + coef[i + 1]) / 3.0f * fac;
    cs[S - 1] = (coef[S - 2] + coef[S - 1] + coef[S - 1]) / 3.0f * fac;

    if (tab < 7) {
        // ---- tridiagonal Thomas factorization (as before) ----
        float2* out2 = g_tri + (tab * C + c) * TILE;
        float wprev = 0.0f;
#pragma unroll
        for (int i = 0; i < S; ++i) {
            float b = 1.0f + 2.0f * cs[i];
            if (i == 0)     b = 1.0f + cs[0];
            if (i == S - 1) b = 1.0f + cs[S - 1];
            float denom = b - cs[i] * wprev + EPSF;
            float invd  = 1.0f / denom;
            float w     = cs[i] * invd;
            out2[i * S + r] = make_float2(invd, w);
            wprev = w;
        }
    } else {
        // ---- pentadiagonal: T~^2 bands + banded LU + derived constants ----
        const int k = tab - 7;
        float4* out4 = g_p4 + (k * C + c) * TILE;
        float*  out1 = g_p1 + (k * C + c) * TILE;

        // T~ = tridiag(a, b, cc): a0=0, c31=0, b includes EPS
        float a[S], b[S], cc[S];
#pragma unroll
        for (int i = 0; i < S; ++i) {
            float bb_ = 1.0f + 2.0f * cs[i];
            if (i == 0)     bb_ = 1.0f + cs[0];
            if (i == S - 1) bb_ = 1.0f + cs[S - 1];
            b[i]  = bb_ + EPSF;
            a[i]  = (i == 0)     ? 0.0f : -cs[i];
            cc[i] = (i == S - 1) ? 0.0f : -cs[i];
        }
        // P = T~ * T~  (pentadiagonal bands)
        float p2m[S], p1m[S], p0[S], p1p[S], p2p[S];
#pragma unroll
        for (int i = 0; i < S; ++i) {
            p2m[i] = (i >= 2)     ? a[i] * a[i - 1]            : 0.0f;
            p1m[i] = (i >= 1)     ? a[i] * (b[i - 1] + b[i])   : 0.0f;
            p0[i]  = b[i] * b[i]
                   + ((i >= 1)     ? a[i]  * cc[i - 1] : 0.0f)
                   + ((i <= S - 2) ? cc[i] * a[i + 1]  : 0.0f);
            p1p[i] = (i <= S - 2) ? cc[i] * (b[i] + b[i + 1])  : 0.0f;
            p2p[i] = (i <= S - 3) ? cc[i] * cc[i + 1]          : 0.0f;
        }
        // banded LU (lower bw 2, upper bw 2, no pivoting)
        float u0[S], u1[S], u2[S];
#pragma unroll
        for (int i = 0; i < S; ++i) {
            float l2 = (i >= 2) ? p2m[i] / u0[i - 2] : 0.0f;
            float tt = p1m[i] - ((i >= 2) ? l2 * u1[i - 2] : 0.0f);
            float l1 = (i >= 1) ? tt / u0[i - 1] : 0.0f;
            u0[i] = p0[i] - ((i >= 2) ? l2 * u2[i - 2] : 0.0f)
                          - ((i >= 1) ? l1 * u1[i - 1] : 0.0f);
            u1[i] = p1p[i] - ((i >= 1) ? l1 * u2[i - 1] : 0.0f);
            u2[i] = p2p[i];
            float inv0 = 1.0f / u0[i];
            float nl1  = (i >= 1) ? -l1 * u0[i - 1] * inv0 : 0.0f;
            float nl2  = (i >= 2) ? -l2 * u0[i - 2] * inv0 : 0.0f;
            out4[i * S + r] = make_float4(inv0, nl1, nl2, -u1[i] * inv0);
            out1[i * S + r] = -u2[i] * inv0;
        }
    }
}

// ---------------------------------------------------------------------------
// Canonical slab frame: slab[h*PAD + w] = value at (h, w).
// DIR=0 (X solve): element (h=lane, w=i)  -> slab index lane*PAD + i
// DIR=1 (Y solve): element (h=i, w=lane)  -> slab index i*PAD + lane
// Every pass reads its input from the slab and writes its result back.
// ---------------------------------------------------------------------------
#define IDX(i) (DIR == 0 ? (lane * PAD + (i)) : ((i) * PAD + lane))

// tridiagonal pass (R13/R14 core)
template <int DIR>
__device__ __forceinline__ void solve_t(const float2* __restrict__ cf2, int lane,
                                        float2* __restrict__ v0,
                                        float2* __restrict__ v1,
                                        float*  __restrict__ warr,
                                        float2* __restrict__ sA,
                                        float2* __restrict__ sB) {
    float2 cb[2][4];
#pragma unroll
    for (int m = 0; m < 4; ++m)
        cb[0][m] = __ldg(&cf2[m * S + lane]);
    float2 dp0 = make_float2(0.0f, 0.0f);
    float2 dp1 = make_float2(0.0f, 0.0f);
#pragma unroll
    for (int blk = 0; blk < 8; ++blk) {
        if (blk < 7) {
#pragma unroll
            for (int m = 0; m < 4; ++m)
                cb[(blk + 1) & 1][m] = __ldg(&cf2[((blk + 1) * 4 + m) * S + lane]);
        }
#pragma unroll
        for (int m = 0; m < 4; ++m) {
            const int i = blk * 4 + m;
            float2 iw = cb[blk & 1][m];
            warr[i] = iw.y;
            float2 t0 = mul2(sA[IDX(i)], make_float2(iw.x, iw.x));
            float2 t1 = mul2(sB[IDX(i)], make_float2(iw.x, iw.x));
            t0 = fma2(make_float2(iw.y, iw.y), dp0, t0);
            t1 = fma2(make_float2(iw.y, iw.y), dp1, t1);
            v0[i] = t0; dp0 = t0;
            v1[i] = t1; dp1 = t1;
        }
    }
    __syncwarp();
    sA[IDX(31)] = v0[31];
    sB[IDX(31)] = v1[31];
#pragma unroll
    for (int i = S - 2; i >= 0; --i) {
        float2 w2 = make_float2(warr[i], warr[i]);
        float2 r0 = fma2(w2, v0[i + 1], v0[i]);
        float2 r1 = fma2(w2, v1[i + 1], v1[i]);
        v0[i] = r0; sA[IDX(i)] = r0;
        v1[i] = r1; sB[IDX(i)] = r1;
    }
    __syncwarp();
}

// pentadiagonal pass (two fused X solves)
template <int DIR>
__device__ __forceinline__ void psolve_t(const float4* __restrict__ cf4,
                                         const float*  __restrict__ cw2, int lane,
                                         float2* __restrict__ v0,
                                         float2* __restrict__ v1,
                                         float*  __restrict__ warr,
                                         float2* __restrict__ sA,
                                         float2* __restrict__ sB) {
    // forward: e_i = u_i*inv0 + nl1*e_{i-1} + nl2*e_{i-2}
    float4 cb[2][2];
    cb[0][0] = __ldg(&cf4[0 * S + lane]);
    cb[0][1] = __ldg(&cf4[1 * S + lane]);
    float2 e1_0 = make_float2(0.f, 0.f), e2_0 = e1_0;   // e_{i-1}, e_{i-2}
    float2 e1_1 = e1_0, e2_1 = e1_0;
#pragma unroll
    for (int blk = 0; blk < 16; ++blk) {
        if (blk < 15) {
            cb[(blk + 1) & 1][0] = __ldg(&cf4[((blk + 1) * 2 + 0) * S + lane]);
            cb[(blk + 1) & 1][1] = __ldg(&cf4[((blk + 1) * 2 + 1) * S + lane]);
        }
#pragma unroll
        for (int m = 0; m < 2; ++m) {
            const int i = blk * 2 + m;
            float4 iw = cb[blk & 1][m];
            warr[i] = iw.w;                               // nw1 for bwd
            float2 t0 = mul2(sA[IDX(i)], make_float2(iw.x, iw.x));
            float2 t1 = mul2(sB[IDX(i)], make_float2(iw.x, iw.x));
            t0 = fma2(make_float2(iw.z, iw.z), e2_0, t0); // off-chain
            t1 = fma2(make_float2(iw.z, iw.z), e2_1, t1);
            t0 = fma2(make_float2(iw.y, iw.y), e1_0, t0); // 4-cyc chain
            t1 = fma2(make_float2(iw.y, iw.y), e1_1, t1);
            v0[i] = t0; e2_0 = e1_0; e1_0 = t0;
            v1[i] = t1; e2_1 = e1_1; e1_1 = t1;
        }
    }
    __syncwarp();
    // backward: x_i = e_i + nw1*x_{i+1} + nw2*x_{i+2}; nw1/nw2 are 0 at the
    // top boundary (precompute guarantees), so the loop is uniform i=31..0.
    float wb[2][4];
#pragma unroll
    for (int m = 0; m < 4; ++m)
        wb[0][m] = __ldg(&cw2[(31 - m) * S + lane]);
    float2 xa0 = make_float2(0.f, 0.f), xb0 = xa0;        // x_{i+1}, x_{i+2}
    float2 xa1 = xa0, xb1 = xa0;
#pragma unroll
    for (int blk = 0; blk < 8; ++blk) {
        if (blk < 7) {
#pragma unroll
            for (int m = 0; m < 4; ++m)
                wb[(blk + 1) & 1][m] = __ldg(&cw2[(31 - ((blk + 1) * 4 + m)) * S + lane]);
        }
#pragma unroll
        for (int m = 0; m < 4; ++m) {
            const int i = 31 - (blk * 4 + m);
            float nw2 = wb[blk & 1][m];
            float2 t0 = fma2(make_float2(nw2, nw2), xb0, v0[i]);   // off-chain
            float2 t1 = fma2(make_float2(nw2, nw2), xb1, v1[i]);
            float2 w1 = make_float2(warr[i], warr[i]);
            float2 x0 = fma2(w1, xa0, t0);                          // chain
            float2 x1 = fma2(w1, xa1, t1);
            sA[IDX(i)] = x0; xb0 = xa0; xa0 = x0;
            sB[IDX(i)] = x1; xb1 = xa1; xa1 = x1;
        }
    }
    __syncwarp();
}
#undef IDX

// ---------------------------------------------------------------------------
// Main fused ADI kernel: ONE warp per CTA, K=4 tiles as TWO f32x2 pairs.
// 11 perfectly direction-alternating passes:
//   X0 | [Y_k, XX_k(penta)] k=0..3 | Y4 | X5
// ---------------------------------------------------------------------------
__global__ __launch_bounds__(32, 8)
void adi_kernel(const float* __restrict__ uin, float* __restrict__ uout) {
    __shared__ float2 sA[S * PAD];
    __shared__ float2 sB[S * PAD];

    const int lane   = threadIdx.x;
    const int nquads = gridDim.x / C;                   // 512
    const int cid    = blockIdx.x / nquads;             // c-major grouping
    const int bg     = blockIdx.x % nquads;             // 0..511 batch-quad
    const int base0  = (4 * bg) * C * TILE + cid * TILE;

    float2 v0[S], v1[S];
    float  warr[S];

    // ---- load: coalesced streaming LDG -> canonical slabs ----
#pragma unroll 8
    for (int i = 0; i < S; ++i) {
        sA[i * PAD + lane] = make_float2(__ldcs(&uin[base0 + 0 * C * TILE + i * S + lane]),
                                         __ldcs(&uin[base0 + 1 * C * TILE + i * S + lane]));
        sB[i * PAD + lane] = make_float2(__ldcs(&uin[base0 + 2 * C * TILE + i * S + lane]),
                                         __ldcs(&uin[base0 + 3 * C * TILE + i * S + lane]));
    }
    __syncwarp();

    const int CT = C * TILE;
    const float2* tri = g_tri + cid * TILE;
    const float4* p4  = g_p4  + cid * TILE;
    const float*  p1  = g_p1  + cid * TILE;

    // X0 @ t=0
    solve_t<0>(tri + 0 * CT, lane, v0, v1, warr, sA, sB);
#pragma unroll 1
    for (int k = 0; k < 4; ++k) {
        // Y_k @ t=0.05+0.1k
        solve_t<1>(tri + (2 + k) * CT, lane, v0, v1, warr, sA, sB);
        // fused double-X @ t=0.1(k+1)  (pentadiagonal)
        psolve_t<0>(p4 + k * CT, p1 + k * CT, lane, v0, v1, warr, sA, sB);
    }
    // Y4 @ t=0.45
    solve_t<1>(tri + 6 * CT, lane, v0, v1, warr, sA, sB);
    // X5 @ t=0.5
    solve_t<0>(tri + 1 * CT, lane, v0, v1, warr, sA, sB);

    // ---- store: canonical slabs -> coalesced streaming STG ----
#pragma unroll 8
    for (int i = 0; i < S; ++i) {
        float2 a = sA[i * PAD + lane];
        float2 b = sB[i * PAD + lane];
        __stcs(&uout[base0 + 0 * C * TILE + i * S + lane], a.x);
        __stcs(&uout[base0 + 1 * C * TILE + i * S + lane], a.y);
        __stcs(&uout[base0 + 2 * C * TILE + i * S + lane], b.x);
        __stcs(&uout[base0 + 3 * C * TILE + i * S + lane], b.y);
    }
}

// ---------------------------------------------------------------------------
extern "C" void kernel_launch(void* const* d_in, const int* in_sizes, int n_in,
                              void* d_out, int out_size) {
    const float* u   = (const float*)d_in[0];
    const float* ab  = (const float*)d_in[1];
    const float* bb  = (const float*)d_in[2];
    const float* atc = (const float*)d_in[3];
    const float* btc = (const float*)d_in[4];
    float* out = (float*)d_out;

    const int B = in_sizes[0] / (C * TILE);   // 2048

    precompute_kernel<<<(11 * C * S + 127) / 128, 128>>>(ab, bb, atc, btc);

    const int nquads = B / 4;                 // 512
    adi_kernel<<<nquads * C, 32>>>(u, out);   // 1536 one-warp CTAs, c-major
}

// round 17
// speedup vs baseline: 1.0618x; 1.0618x over previous
#include <cuda_runtime.h>

#define EPSF 1e-6f
#define S 32
#define C 3
#define TILE (S * S)   // 1024
#define PAD 33

// Precomputed Thomas factorizations, 11 time-indices (j=0..5 x-dir, 6..10 y-dir):
//   g_cf2[(j*C+c)*TILE + i*S + r] = (invd, w)
// c_star = -w, so backward sweep is x_i = d_i + w_i * x_{i+1}.
__device__ __align__(128) float2 g_cf2[11 * C * TILE];

// ---------------------------------------------------------------------------
// packed f32x2 + cache-hint helpers (PTX-only)
// ---------------------------------------------------------------------------
__device__ __forceinline__ float2 fma2(float2 a, float2 b, float2 c) {
    unsigned long long au = *reinterpret_cast<unsigned long long*>(&a);
    unsigned long long bu = *reinterpret_cast<unsigned long long*>(&b);
    unsigned long long cu = *reinterpret_cast<unsigned long long*>(&c);
    unsigned long long du;
    asm("fma.rn.f32x2 %0, %1, %2, %3;" : "=l"(du) : "l"(au), "l"(bu), "l"(cu));
    return *reinterpret_cast<float2*>(&du);
}
__device__ __forceinline__ float2 mul2(float2 a, float2 b) {
    unsigned long long au = *reinterpret_cast<unsigned long long*>(&a);
    unsigned long long bu = *reinterpret_cast<unsigned long long*>(&b);
    unsigned long long du;
    asm("mul.rn.f32x2 %0, %1, %2;" : "=l"(du) : "l"(au), "l"(bu));
    return *reinterpret_cast<float2*>(&du);
}
// coefficient load: non-coherent + L1 evict_last (pin hot table lines in L1D)
__device__ __forceinline__ float2 ldg_el(const float2* p) {
    float2 r;
    asm("ld.global.nc.L1::evict_last.v2.f32 {%0, %1}, [%2];"
        : "=f"(r.x), "=f"(r.y) : "l"(p));
    return r;
}

// ---------------------------------------------------------------------------
// Precompute kernel: one thread per (timeIdx, c, row). 11*3*32 = 1056 threads.
// Divides replaced by fast reciprocal (MUFU.RCP path) — the serial divide
// chain was the bulk of this kernel's duration.
// ---------------------------------------------------------------------------
__global__ void precompute_kernel(const float* __restrict__ ab,
                                  const float* __restrict__ bb,
                                  const float* __restrict__ atc,
                                  const float* __restrict__ btc) {
    int tid = blockIdx.x * blockDim.x + threadIdx.x;
    if (tid >= 11 * C * S) return;
    int j   = tid / (C * S);
    int rem = tid % (C * S);
    int c   = rem / S;
    int r   = rem % S;

    float t, fac;
    const float* bp;
    const float* tp;
    int stride;
    if (j < 6) {                       // x-direction, t = j*DT, dt = DT/2
        t   = (float)(j * 0.1);
        fac = 0.05f;
        bp  = ab + (c * S + r) * S;
        tp  = atc + (c * S + r) * S;
        stride = 1;
    } else {                           // y-direction, t = DT/2 + jy*DT, dt = DT
        int jy = j - 6;
        t   = (float)(0.05 + jy * 0.1);
        fac = 0.1f;
        bp  = bb + c * TILE + r;
        tp  = btc + c * TILE + r;
        stride = S;
    }
    float2* out2 = g_cf2 + (j * C + c) * TILE;

    float coef[S];
#pragma unroll
    for (int i = 0; i < S; ++i)
        coef[i] = fmaxf(bp[i * stride] + t * tp[i * stride], EPSF);

    float cs[S];
    cs[0] = (coef[0] + coef[0] + coef[1]) * (1.0f / 3.0f) * fac;
#pragma unroll
    for (int i = 1; i < S - 1; ++i)
        cs[i] = (coef[i - 1] + coef[i] + coef[i + 1]) * (1.0f / 3.0f) * fac;
    cs[S - 1] = (coef[S - 2] + coef[S - 1] + coef[S - 1]) * (1.0f / 3.0f) * fac;

    float wprev = 0.0f;
#pragma unroll
    for (int i = 0; i < S; ++i) {
        float b = 1.0f + 2.0f * cs[i];
        if (i == 0)     b = 1.0f + cs[0];
        if (i == S - 1) b = 1.0f + cs[S - 1];
        float denom = b - cs[i] * wprev + EPSF;
        float invd  = __fdividef(1.0f, denom);   // fast rcp path
        float w     = cs[i] * invd;
        out2[i * S + r] = make_float2(invd, w);
        wprev = w;
    }
}

// ---------------------------------------------------------------------------
// Fused-transpose Thomas solve (R13/R14 core).
// Canonical slab frame: slab[h*PAD + w] = value at (h, w).
// DIR=0 (X solve): element (h=lane, w=i)  -> slab index lane*PAD + i
// DIR=1 (Y solve): element (h=i, w=lane)  -> slab index i*PAD + lane
// ---------------------------------------------------------------------------
template <int DIR, bool INS, bool OUTS>
__device__ __forceinline__ void solve_t(const float2* __restrict__ cf2, int lane,
                                        float2* __restrict__ v0,
                                        float2* __restrict__ v1,
                                        float*  __restrict__ warr,
                                        float2* __restrict__ sA,
                                        float2* __restrict__ sB) {
#define IDX(i) (DIR == 0 ? (lane * PAD + (i)) : ((i) * PAD + lane))
    float2 cb[2][4];
#pragma unroll
    for (int m = 0; m < 4; ++m)
        cb[0][m] = ldg_el(&cf2[m * S + lane]);
    float2 dp0 = make_float2(0.0f, 0.0f);
    float2 dp1 = make_float2(0.0f, 0.0f);
#pragma unroll
    for (int blk = 0; blk < 8; ++blk) {
        if (blk < 7) {
#pragma unroll
            for (int m = 0; m < 4; ++m)
                cb[(blk + 1) & 1][m] = ldg_el(&cf2[((blk + 1) * 4 + m) * S + lane]);
        }
#pragma unroll
        for (int m = 0; m < 4; ++m) {
            const int i = blk * 4 + m;
            float2 iw = cb[blk & 1][m];
            warr[i] = iw.y;
            float2 x0 = INS ? sA[IDX(i)] : v0[i];
            float2 x1 = INS ? sB[IDX(i)] : v1[i];
            float2 inv2 = make_float2(iw.x, iw.x);
            float2 w2   = make_float2(iw.y, iw.y);
            float2 t0 = mul2(x0, inv2);
            float2 t1 = mul2(x1, inv2);
            t0 = fma2(w2, dp0, t0);
            t1 = fma2(w2, dp1, t1);
            v0[i] = t0; dp0 = t0;
            v1[i] = t1; dp1 = t1;
        }
    }
    __syncwarp();
    if (OUTS) {
        sA[IDX(31)] = v0[31];
        sB[IDX(31)] = v1[31];
    }
#pragma unroll
    for (int i = S - 2; i >= 0; --i) {
        float2 w2 = make_float2(warr[i], warr[i]);
        float2 r0 = fma2(w2, v0[i + 1], v0[i]);
        float2 r1 = fma2(w2, v1[i + 1], v1[i]);
        v0[i] = r0;
        v1[i] = r1;
        if (OUTS) {
            sA[IDX(i)] = r0;
            sB[IDX(i)] = r1;
        }
    }
    __syncwarp();
#undef IDX
}

// ---------------------------------------------------------------------------
// Main fused ADI kernel: ONE warp per CTA, K=4 tiles as TWO f32x2 pairs.
// c-major block order, streaming u-tile io, evict_last coefficient loads.
// ---------------------------------------------------------------------------
__global__ __launch_bounds__(32, 8)
void adi_kernel(const float* __restrict__ uin, float* __restrict__ uout) {
    __shared__ float2 sA[S * PAD];   // pair0 canonical slab
    __shared__ float2 sB[S * PAD];   // pair1 canonical slab

    const int lane   = threadIdx.x;
    const int nquads = gridDim.x / C;                   // 512
    const int cid    = blockIdx.x / nquads;             // c-major grouping
    const int bg     = blockIdx.x % nquads;             // 0..511 batch-quad
    const int base0  = (4 * bg) * C * TILE + cid * TILE;

    float2 v0[S], v1[S];
    float  warr[S];

    // ---- load: coalesced streaming LDG -> canonical slabs ----
#pragma unroll 8
    for (int i = 0; i < S; ++i) {
        sA[i * PAD + lane] = make_float2(__ldcs(&uin[base0 + 0 * C * TILE + i * S + lane]),
                                         __ldcs(&uin[base0 + 1 * C * TILE + i * S + lane]));
        sB[i * PAD + lane] = make_float2(__ldcs(&uin[base0 + 2 * C * TILE + i * S + lane]),
                                         __ldcs(&uin[base0 + 3 * C * TILE + i * S + lane]));
    }
    __syncwarp();

    const float2* tab = g_cf2 + cid * TILE;   // + j*C*TILE per time index
    const int CT = C * TILE;

    // X0: slab -> slab
    solve_t<0, true, true>(tab + 0 * CT, lane, v0, v1, warr, sA, sB);
    // [Y_it (slab->slab), X_{it+1} (slab->regs), X_{it+1} (regs->slab)] x4
#pragma unroll 1
    for (int it = 0; it < 4; ++it) {
        solve_t<1, true, true >(tab + (6 + it) * CT, lane, v0, v1, warr, sA, sB);
        solve_t<0, true, false>(tab + (it + 1) * CT, lane, v0, v1, warr, sA, sB);
        solve_t<0, false, true>(tab + (it + 1) * CT, lane, v0, v1, warr, sA, sB);
    }
    // Y4: slab -> slab
    solve_t<1, true, true>(tab + 10 * CT, lane, v0, v1, warr, sA, sB);
    // X5: slab -> slab (canonical frame)
    solve_t<0, true, true>(tab + 5 * CT, lane, v0, v1, warr, sA, sB);

    // ---- store: canonical slabs -> coalesced streaming STG ----
#pragma unroll 8
    for (int i = 0; i < S; ++i) {
        float2 a = sA[i * PAD + lane];
        float2 b = sB[i * PAD + lane];
        __stcs(&uout[base0 + 0 * C * TILE + i * S + lane], a.x);
        __stcs(&uout[base0 + 1 * C * TILE + i * S + lane], a.y);
        __stcs(&uout[base0 + 2 * C * TILE + i * S + lane], b.x);
        __stcs(&uout[base0 + 3 * C * TILE + i * S + lane], b.y);
    }
}

// ---------------------------------------------------------------------------
extern "C" void kernel_launch(void* const* d_in, const int* in_sizes, int n_in,
                              void* d_out, int out_size) {
    const float* u   = (const float*)d_in[0];
    const float* ab  = (const float*)d_in[1];
    const float* bb  = (const float*)d_in[2];
    const float* atc = (const float*)d_in[3];
    const float* btc = (const float*)d_in[4];
    float* out = (float*)d_out;

    const int B = in_sizes[0] / (C * TILE);   // 2048

    precompute_kernel<<<(11 * C * S + 127) / 128, 128>>>(ab, bb, atc, btc);

    const int nquads = B / 4;                 // 512
    adi_kernel<<<nquads * C, 32>>>(u, out);   // 1536 one-warp CTAs, c-major
}